// round 1
// baseline (speedup 1.0000x reference)
#include <cuda_runtime.h>

// ============================================================================
// Transformer-XL relative-position attention (fp32 baseline)
// B=2, T=1024, F=1024, H=16, DK=DV=64, OUT=1024
//
// Math note: the reference's rel_shift_left/right pair collapses to
//   BD[i,j] = (q+v_bias)_i . p[T-1-|i-j|]
// with full (non-causal) softmax over j. So:
//   S[b,h,i,j] = ( (q_i+u).k_j + (q_i+v).p[1023-|i-j|] ) / 8
//   out = softmax(S) @ V, then output projection.
// ============================================================================

#define BB 2
#define TT 1024
#define FF 1024
#define HH 16
#define DKK 64

// ---- static device scratch (allocation-free rule) ----
__device__ float g_q[BB * TT * FF];         // 8 MB   (B*T, H*DK)
__device__ float g_k[BB * TT * FF];         // 8 MB
__device__ float g_v[BB * TT * FF];         // 8 MB
__device__ float g_p[TT * FF];              // 4 MB   (T, H*DK)
__device__ float g_s[33554432];             // 128 MB (B*H, T, T) scores/attn
__device__ float g_x[BB * TT * FF];         // 8 MB   (B*T, H*DV)

// ============================================================================
// Generic projection GEMM: C[M][1024] = A[M][1024] @ W[1024][1024]^T + bias
// 128x128 tile, BK=16, 256 threads, 8x8 micro-tile per thread.
// ============================================================================
__global__ __launch_bounds__(256) void sgemm_bias_kernel(
    const float* __restrict__ A, const float* __restrict__ W,
    const float* __restrict__ bias, float* __restrict__ C)
{
    const int n0 = blockIdx.x * 128;
    const int m0 = blockIdx.y * 128;

    __shared__ float Ash[16][129];   // [k][m]
    __shared__ float Wsh[16][129];   // [k][n]

    const int tid = threadIdx.x;
    const int tr = tid >> 4;         // 0..15 -> 8 rows each
    const int tc = tid & 15;         // 0..15 -> cols tc*4..+3 and tc*4+64..+3

    float acc[8][8];
#pragma unroll
    for (int r = 0; r < 8; r++)
#pragma unroll
        for (int c = 0; c < 8; c++) acc[r][c] = 0.0f;

    for (int kk = 0; kk < 1024; kk += 16) {
        // load A tile (128x16) and W tile (128x16), transposed into smem
#pragma unroll
        for (int l = 0; l < 2; l++) {
            int idx = tid + l * 256;        // 0..511
            int row = idx >> 2;             // 0..127
            int c4  = idx & 3;              // 0..3
            float4 a = *(const float4*)(A + (size_t)(m0 + row) * 1024 + kk + c4 * 4);
            Ash[c4 * 4 + 0][row] = a.x;
            Ash[c4 * 4 + 1][row] = a.y;
            Ash[c4 * 4 + 2][row] = a.z;
            Ash[c4 * 4 + 3][row] = a.w;
            float4 w = *(const float4*)(W + (size_t)(n0 + row) * 1024 + kk + c4 * 4);
            Wsh[c4 * 4 + 0][row] = w.x;
            Wsh[c4 * 4 + 1][row] = w.y;
            Wsh[c4 * 4 + 2][row] = w.z;
            Wsh[c4 * 4 + 3][row] = w.w;
        }
        __syncthreads();

#pragma unroll
        for (int k = 0; k < 16; k++) {
            float a[8], b[8];
#pragma unroll
            for (int r = 0; r < 8; r++) a[r] = Ash[k][tr * 8 + r];
#pragma unroll
            for (int c = 0; c < 8; c++)
                b[c] = Wsh[k][tc * 4 + (c & 3) + ((c >> 2) * 64)];
#pragma unroll
            for (int r = 0; r < 8; r++)
#pragma unroll
                for (int c = 0; c < 8; c++)
                    acc[r][c] = fmaf(a[r], b[c], acc[r][c]);
        }
        __syncthreads();
    }

#pragma unroll
    for (int r = 0; r < 8; r++) {
        int row = m0 + tr * 8 + r;
#pragma unroll
        for (int c = 0; c < 8; c++) {
            int col = n0 + tc * 4 + (c & 3) + ((c >> 2) * 64);
            C[(size_t)row * 1024 + col] = acc[r][c] + bias[col];
        }
    }
}

// ============================================================================
// Scores: S[bh][i][j] = ((q_i+u).k_j + (q_i+v).p[1023-|i-j|]) * 0.125
// 64x64 tile per block, 256 threads, 4x4 micro-tile, dk split into 2x32 chunks.
// Toeplitz structure: a thread's 4x4 micro-tile needs only 7 p-rows per k-step.
// ============================================================================
__global__ __launch_bounds__(256) void scores_kernel(
    const float* __restrict__ u_bias, const float* __restrict__ v_bias)
{
    const int j0 = blockIdx.x * 64;
    const int i0 = blockIdx.y * 64;
    const int bh = blockIdx.z;
    const int b  = bh >> 4;
    const int h  = bh & 15;

    __shared__ float qsh[64][36];
    __shared__ float ksh[64][36];
    __shared__ float psh[127][36];
    __shared__ float ush[64];
    __shared__ float vsh[64];

    const int tid = threadIdx.x;
    if (tid < 16)       ((float4*)ush)[tid]      = ((const float4*)(u_bias + h * 64))[tid];
    else if (tid < 32)  ((float4*)vsh)[tid - 16] = ((const float4*)(v_bias + h * 64))[tid - 16];

    const int tr  = tid >> 4;
    const int tc  = tid & 15;
    const int ii0 = tr * 4;
    const int jj0 = tc * 4;
    const int dl0 = ii0 - jj0 + 63;     // in [3,123]; need rows dl0-3..dl0+3

    float acc[4][4];
#pragma unroll
    for (int r = 0; r < 4; r++)
#pragma unroll
        for (int c = 0; c < 4; c++) acc[r][c] = 0.0f;

    const float* qbase = g_q + (size_t)(b * 1024) * 1024 + h * 64;
    const float* kbase = g_k + (size_t)(b * 1024) * 1024 + h * 64;
    const float* pbase = g_p + h * 64;

    for (int ch = 0; ch < 2; ch++) {
        const int kk = ch * 32;
        __syncthreads();
        // q/k tiles: 64 rows x 8 float4
#pragma unroll
        for (int l = 0; l < 2; l++) {
            int idx = tid + l * 256;    // 0..511
            int row = idx >> 3;
            int c4  = idx & 7;
            *(float4*)&qsh[row][c4 * 4] =
                *(const float4*)(qbase + (size_t)(i0 + row) * 1024 + kk + c4 * 4);
            *(float4*)&ksh[row][c4 * 4] =
                *(const float4*)(kbase + (size_t)(j0 + row) * 1024 + kk + c4 * 4);
        }
        // p window: 127 rows x 8 float4, row dloc maps to p[1023-|i0-j0+dloc-63|]
        for (int idx = tid; idx < 127 * 8; idx += 256) {
            int row = idx >> 3;
            int c4  = idx & 7;
            int d   = i0 - j0 + row - 63;
            int pidx = 1023 - (d < 0 ? -d : d);
            *(float4*)&psh[row][c4 * 4] =
                *(const float4*)(pbase + (size_t)pidx * 1024 + kk + c4 * 4);
        }
        __syncthreads();

#pragma unroll
        for (int kq = 0; kq < 8; kq++) {
            float4 uu = *(float4*)&ush[kk + kq * 4];
            float4 vv = *(float4*)&vsh[kk + kq * 4];
            float4 kc[4];
#pragma unroll
            for (int c = 0; c < 4; c++) kc[c] = *(float4*)&ksh[jj0 + c][kq * 4];
            float4 pr[7];
#pragma unroll
            for (int s = 0; s < 7; s++) pr[s] = *(float4*)&psh[dl0 - 3 + s][kq * 4];
#pragma unroll
            for (int r = 0; r < 4; r++) {
                float4 qq = *(float4*)&qsh[ii0 + r][kq * 4];
                float4 qu, qv;
                qu.x = qq.x + uu.x; qu.y = qq.y + uu.y; qu.z = qq.z + uu.z; qu.w = qq.w + uu.w;
                qv.x = qq.x + vv.x; qv.y = qq.y + vv.y; qv.z = qq.z + vv.z; qv.w = qq.w + vv.w;
#pragma unroll
                for (int c = 0; c < 4; c++) {
                    float4 kv = kc[c];
                    float4 pv = pr[3 + r - c];
                    float t = acc[r][c];
                    t = fmaf(qu.x, kv.x, t);
                    t = fmaf(qu.y, kv.y, t);
                    t = fmaf(qu.z, kv.z, t);
                    t = fmaf(qu.w, kv.w, t);
                    t = fmaf(qv.x, pv.x, t);
                    t = fmaf(qv.y, pv.y, t);
                    t = fmaf(qv.z, pv.z, t);
                    t = fmaf(qv.w, pv.w, t);
                    acc[r][c] = t;
                }
            }
        }
    }

    float* srow = g_s + ((size_t)bh << 20);
#pragma unroll
    for (int r = 0; r < 4; r++) {
        float4 o;
        o.x = acc[r][0] * 0.125f;
        o.y = acc[r][1] * 0.125f;
        o.z = acc[r][2] * 0.125f;
        o.w = acc[r][3] * 0.125f;
        *(float4*)(srow + (size_t)(i0 + ii0 + r) * 1024 + j0 + jj0) = o;
    }
}

// ============================================================================
// Row softmax over g_s (32768 rows of 1024), in place.
// ============================================================================
__global__ __launch_bounds__(256) void softmax_kernel()
{
    __shared__ float redm[8];
    __shared__ float reds[8];
    const size_t row = blockIdx.x;
    float4* p4 = (float4*)(g_s + (row << 10));
    const int tid  = threadIdx.x;
    const int lane = tid & 31;
    const int wid  = tid >> 5;

    float4 v = p4[tid];
    float m = fmaxf(fmaxf(v.x, v.y), fmaxf(v.z, v.w));
#pragma unroll
    for (int o = 16; o; o >>= 1) m = fmaxf(m, __shfl_xor_sync(0xffffffffu, m, o));
    if (lane == 0) redm[wid] = m;
    __syncthreads();
    float bm = redm[0];
#pragma unroll
    for (int i = 1; i < 8; i++) bm = fmaxf(bm, redm[i]);

    v.x = expf(v.x - bm);
    v.y = expf(v.y - bm);
    v.z = expf(v.z - bm);
    v.w = expf(v.w - bm);
    float s = v.x + v.y + v.z + v.w;
#pragma unroll
    for (int o = 16; o; o >>= 1) s += __shfl_xor_sync(0xffffffffu, s, o);
    if (lane == 0) reds[wid] = s;
    __syncthreads();
    float tot = 0.0f;
#pragma unroll
    for (int i = 0; i < 8; i++) tot += reds[i];
    float inv = 1.0f / tot;
    v.x *= inv; v.y *= inv; v.z *= inv; v.w *= inv;
    p4[tid] = v;
}

// ============================================================================
// PV: x[b][t][h*64+d] = sum_s attn[bh][t][s] * V[b][s][h*64+d]
// 128 rows x 64 cols per block, 256 threads, 8x4 micro-tile, 32-wide k chunks.
// ============================================================================
__global__ __launch_bounds__(256) void pv_kernel()
{
    const int i0 = blockIdx.x * 128;
    const int bh = blockIdx.y;
    const int b  = bh >> 4;
    const int h  = bh & 15;

    __shared__ float Ssh[32][129];  // [k][row]
    __shared__ float Vsh[32][68];   // [k][d]

    const int tid = threadIdx.x;
    const int tr = tid >> 4;        // 0..15 -> 8 rows each
    const int tc = tid & 15;        // 0..15 -> 4 cols each

    float acc[8][4];
#pragma unroll
    for (int r = 0; r < 8; r++)
#pragma unroll
        for (int c = 0; c < 4; c++) acc[r][c] = 0.0f;

    const float* sbase = g_s + ((size_t)bh << 20);
    const float* vbase = g_v + (size_t)(b * 1024) * 1024 + h * 64;

    for (int s0 = 0; s0 < 1024; s0 += 32) {
        __syncthreads();
        // attn tile 128x32, transposed into Ssh
#pragma unroll
        for (int l = 0; l < 4; l++) {
            int idx = tid + l * 256;    // 0..1023
            int row = idx >> 3;         // 0..127
            int c4  = idx & 7;
            float4 sv = *(const float4*)(sbase + (size_t)(i0 + row) * 1024 + s0 + c4 * 4);
            Ssh[c4 * 4 + 0][row] = sv.x;
            Ssh[c4 * 4 + 1][row] = sv.y;
            Ssh[c4 * 4 + 2][row] = sv.z;
            Ssh[c4 * 4 + 3][row] = sv.w;
        }
        // V tile 32x64
#pragma unroll
        for (int l = 0; l < 2; l++) {
            int idx = tid + l * 256;    // 0..511
            int row = idx >> 4;         // 0..31
            int c4  = idx & 15;
            *(float4*)&Vsh[row][c4 * 4] =
                *(const float4*)(vbase + (size_t)(s0 + row) * 1024 + c4 * 4);
        }
        __syncthreads();

#pragma unroll
        for (int k = 0; k < 32; k++) {
            float a[8], bfr[4];
#pragma unroll
            for (int r = 0; r < 8; r++) a[r] = Ssh[k][tr * 8 + r];
#pragma unroll
            for (int c = 0; c < 4; c++) bfr[c] = Vsh[k][tc * 4 + c];
#pragma unroll
            for (int r = 0; r < 8; r++)
#pragma unroll
                for (int c = 0; c < 4; c++)
                    acc[r][c] = fmaf(a[r], bfr[c], acc[r][c]);
        }
    }

#pragma unroll
    for (int r = 0; r < 8; r++) {
        int row = b * 1024 + i0 + tr * 8 + r;
        float4 o;
        o.x = acc[r][0]; o.y = acc[r][1]; o.z = acc[r][2]; o.w = acc[r][3];
        *(float4*)(g_x + (size_t)row * 1024 + h * 64 + tc * 4) = o;
    }
}

// ============================================================================
// Host launcher
// ============================================================================
extern "C" void kernel_launch(void* const* d_in, const int* in_sizes, int n_in,
                              void* d_out, int out_size)
{
    const float* query   = (const float*)d_in[0];
    const float* key     = (const float*)d_in[1];
    const float* value   = (const float*)d_in[2];
    const float* pos_emb = (const float*)d_in[3];
    const float* Wq = (const float*)d_in[4];
    const float* bq = (const float*)d_in[5];
    const float* Wk = (const float*)d_in[6];
    const float* bk = (const float*)d_in[7];
    const float* Wv = (const float*)d_in[8];
    const float* bv = (const float*)d_in[9];
    const float* Wp = (const float*)d_in[10];
    const float* bp = (const float*)d_in[11];
    const float* Wo = (const float*)d_in[12];
    const float* bo = (const float*)d_in[13];
    const float* u_bias = (const float*)d_in[14];
    const float* v_bias = (const float*)d_in[15];
    float* out = (float*)d_out;

    static float *pq = nullptr, *pk = nullptr, *pv = nullptr, *pp = nullptr, *px = nullptr;
    if (!pq) {
        cudaGetSymbolAddress((void**)&pq, g_q);
        cudaGetSymbolAddress((void**)&pk, g_k);
        cudaGetSymbolAddress((void**)&pv, g_v);
        cudaGetSymbolAddress((void**)&pp, g_p);
        cudaGetSymbolAddress((void**)&px, g_x);
    }

    dim3 blk(256);
    // projections
    sgemm_bias_kernel<<<dim3(8, 16), blk>>>(query,   Wq, bq, pq);
    sgemm_bias_kernel<<<dim3(8, 16), blk>>>(key,     Wk, bk, pk);
    sgemm_bias_kernel<<<dim3(8, 16), blk>>>(value,   Wv, bv, pv);
    sgemm_bias_kernel<<<dim3(8, 8),  blk>>>(pos_emb, Wp, bp, pp);
    // attention scores with relative-position term
    scores_kernel<<<dim3(16, 16, 32), blk>>>(u_bias, v_bias);
    // softmax
    softmax_kernel<<<32768, 256>>>();
    // attn @ V
    pv_kernel<<<dim3(8, 32), blk>>>();
    // output projection
    sgemm_bias_kernel<<<dim3(8, 16), blk>>>(px, Wo, bo, out);
}

// round 2
// speedup vs baseline: 1.7694x; 1.7694x over previous
#include <cuda_runtime.h>
#include <cuda_bf16.h>
#include <cstdint>

// ============================================================================
// Transformer-XL relative-position attention — bf16x3 tensor-core version
// B=2, T=1024, F=1024, H=16, DK=DV=64, OUT=1024
//
//   BD[i,j] = (q+v_bias)_i . p[1023-|i-j|]   (rel-shift pair collapses)
//   S = ((q+u).k^T + BD)/8 ; out = softmax(S) @ V @ Wo^T + bo
//
// Every GEMM runs as mma.sync.m16n8k16.bf16 with the 3-term split trick:
//   x = hi(x) + lo(x) in bf16;  A.B ~= Ah.Bh + Ah.Bl + Al.Bh  (fp32 accum)
// giving ~16 effective mantissa bits (rel err ~1e-5 per stage).
// ============================================================================

#define BB 2
#define TT 1024
#define FF 1024

// ---- static device scratch ----
__device__ float g_q[BB * TT * FF];     // (B*T, H*64)
__device__ float g_k[BB * TT * FF];
__device__ float g_v[BB * TT * FF];
__device__ float g_p[TT * FF];          // (T, H*64)
__device__ float g_s[33554432];         // (B*H, T, T)
__device__ float g_x[BB * TT * FF];

// ---------------------------------------------------------------------------
// helpers
// ---------------------------------------------------------------------------
__device__ __forceinline__ void split2(float x0, float x1, uint32_t& hi, uint32_t& lo)
{
    __nv_bfloat16 h0 = __float2bfloat16_rn(x0);
    __nv_bfloat16 h1 = __float2bfloat16_rn(x1);
    float r0 = x0 - __bfloat162float(h0);
    float r1 = x1 - __bfloat162float(h1);
    __nv_bfloat16 l0 = __float2bfloat16_rn(r0);
    __nv_bfloat16 l1 = __float2bfloat16_rn(r1);
    hi = (uint32_t)__bfloat16_as_ushort(h0) | ((uint32_t)__bfloat16_as_ushort(h1) << 16);
    lo = (uint32_t)__bfloat16_as_ushort(l0) | ((uint32_t)__bfloat16_as_ushort(l1) << 16);
}

__device__ __forceinline__ void mma16(float* c, const uint32_t* a, const uint32_t* b)
{
    asm volatile(
        "mma.sync.aligned.m16n8k16.row.col.f32.bf16.bf16.f32 "
        "{%0,%1,%2,%3}, {%4,%5,%6,%7}, {%8,%9}, {%0,%1,%2,%3};"
        : "+f"(c[0]), "+f"(c[1]), "+f"(c[2]), "+f"(c[3])
        : "r"(a[0]), "r"(a[1]), "r"(a[2]), "r"(a[3]), "r"(b[0]), "r"(b[1]));
}

// ============================================================================
// Projection GEMM: C[M][1024] = A[M][1024] @ W[1024][1024]^T + bias
// 128x128 block tile, BK=32, 256 threads (8 warps, 2x4), warp tile 64x32.
// ============================================================================
#define PSTR 20   // uint32 pairs per smem row (16 pairs + pad)

__global__ __launch_bounds__(256, 1) void gemm_bias_mma(
    const float* __restrict__ A, const float* __restrict__ W,
    const float* __restrict__ bias, float* __restrict__ C)
{
    const int n0 = blockIdx.x * 128;
    const int m0 = blockIdx.y * 128;

    __shared__ uint32_t Ah[128 * PSTR], Al[128 * PSTR];
    __shared__ uint32_t Wh[128 * PSTR], Wl[128 * PSTR];

    const int tid  = threadIdx.x;
    const int warp = tid >> 5;
    const int lane = tid & 31;
    const int wr   = warp >> 2;          // 0..1
    const int wc   = warp & 3;           // 0..3
    const int g    = lane >> 2;          // 0..7
    const int tg   = lane & 3;           // 0..3

    float acc[4][4][4];
#pragma unroll
    for (int mt = 0; mt < 4; mt++)
#pragma unroll
        for (int nt = 0; nt < 4; nt++)
#pragma unroll
            for (int e = 0; e < 4; e++) acc[mt][nt][e] = 0.0f;

    for (int kk = 0; kk < 1024; kk += 32) {
        __syncthreads();
#pragma unroll
        for (int l = 0; l < 4; l++) {
            int idx = tid + l * 256;     // 0..1023
            int row = idx >> 3;          // 0..127
            int c4  = idx & 7;           // 0..7
            float4 a = *(const float4*)(A + (size_t)(m0 + row) * 1024 + kk + c4 * 4);
            uint32_t h0, l0, h1, l1;
            split2(a.x, a.y, h0, l0);
            split2(a.z, a.w, h1, l1);
            *(uint2*)&Ah[row * PSTR + c4 * 2] = make_uint2(h0, h1);
            *(uint2*)&Al[row * PSTR + c4 * 2] = make_uint2(l0, l1);
            float4 w = *(const float4*)(W + (size_t)(n0 + row) * 1024 + kk + c4 * 4);
            split2(w.x, w.y, h0, l0);
            split2(w.z, w.w, h1, l1);
            *(uint2*)&Wh[row * PSTR + c4 * 2] = make_uint2(h0, h1);
            *(uint2*)&Wl[row * PSTR + c4 * 2] = make_uint2(l0, l1);
        }
        __syncthreads();

#pragma unroll
        for (int ks = 0; ks < 2; ks++) {
            const int p0 = ks * 8 + tg;
            const int p1 = p0 + 4;
            uint32_t ah[4][4], al4[4][4], bh[4][2], bl[4][2];
#pragma unroll
            for (int mt = 0; mt < 4; mt++) {
                int r = wr * 64 + mt * 16 + g;
                ah[mt][0] = Ah[r * PSTR + p0];
                ah[mt][1] = Ah[(r + 8) * PSTR + p0];
                ah[mt][2] = Ah[r * PSTR + p1];
                ah[mt][3] = Ah[(r + 8) * PSTR + p1];
                al4[mt][0] = Al[r * PSTR + p0];
                al4[mt][1] = Al[(r + 8) * PSTR + p0];
                al4[mt][2] = Al[r * PSTR + p1];
                al4[mt][3] = Al[(r + 8) * PSTR + p1];
            }
#pragma unroll
            for (int nt = 0; nt < 4; nt++) {
                int n = wc * 32 + nt * 8 + g;
                bh[nt][0] = Wh[n * PSTR + p0];
                bh[nt][1] = Wh[n * PSTR + p1];
                bl[nt][0] = Wl[n * PSTR + p0];
                bl[nt][1] = Wl[n * PSTR + p1];
            }
#pragma unroll
            for (int mt = 0; mt < 4; mt++)
#pragma unroll
                for (int nt = 0; nt < 4; nt++) {
                    mma16(acc[mt][nt], ah[mt], bh[nt]);
                    mma16(acc[mt][nt], ah[mt], bl[nt]);
                    mma16(acc[mt][nt], al4[mt], bh[nt]);
                }
        }
    }

#pragma unroll
    for (int nt = 0; nt < 4; nt++) {
        int col = n0 + wc * 32 + nt * 8 + tg * 2;
        float b0 = bias[col], b1 = bias[col + 1];
#pragma unroll
        for (int mt = 0; mt < 4; mt++) {
            int row = m0 + wr * 64 + mt * 16 + g;
            *(float2*)(C + (size_t)row * 1024 + col) =
                make_float2(acc[mt][nt][0] + b0, acc[mt][nt][1] + b1);
            *(float2*)(C + (size_t)(row + 8) * 1024 + col) =
                make_float2(acc[mt][nt][2] + b0, acc[mt][nt][3] + b1);
        }
    }
}

// ============================================================================
// Scores: S[bh][i][j] = ((q_i+u).k_j + (q_i+v).p[1023-|i-j|]) / 8
// Per block: 64(i) x 64(j) tile. AC = (q+u)@k^T (64x64), W = (q+v)@pwin^T
// (64x128, Toeplitz window), gather-combine in smem epilogue.
// ============================================================================
#define SSTR 18

__global__ __launch_bounds__(256, 1) void scores_mma(
    const float* __restrict__ u_bias, const float* __restrict__ v_bias)
{
    const int j0 = blockIdx.x * 64;
    const int i0 = blockIdx.y * 64;
    const int bh = blockIdx.z;
    const int b  = bh >> 4;
    const int h  = bh & 15;

    __shared__ __align__(16) uint32_t sbuf[11520];
    uint32_t* QUH = sbuf + 0;
    uint32_t* QUL = sbuf + 1152;
    uint32_t* QVH = sbuf + 2304;
    uint32_t* QVL = sbuf + 3456;
    uint32_t* KH  = sbuf + 4608;
    uint32_t* KL  = sbuf + 5760;
    uint32_t* PH  = sbuf + 6912;   // 128*18
    uint32_t* PL  = sbuf + 9216;
    float*    Wsm = (float*)sbuf;  // reused after mainloop: 64 x 130

    __shared__ float ush[64], vsh[64];

    const int tid  = threadIdx.x;
    const int warp = tid >> 5;
    const int lane = tid & 31;
    const int wr   = warp >> 2;
    const int wc   = warp & 3;
    const int g    = lane >> 2;
    const int tg   = lane & 3;

    if (tid < 16)      ((float4*)ush)[tid]      = ((const float4*)(u_bias + h * 64))[tid];
    else if (tid < 32) ((float4*)vsh)[tid - 16] = ((const float4*)(v_bias + h * 64))[tid - 16];

    const float* qbase = g_q + (size_t)(b * 1024) * 1024 + h * 64;
    const float* kbase = g_k + (size_t)(b * 1024) * 1024 + h * 64;
    const float* pbase = g_p + h * 64;

    float acc_ac[2][2][4];
    float acc_w[2][4][4];
#pragma unroll
    for (int mt = 0; mt < 2; mt++) {
#pragma unroll
        for (int nt = 0; nt < 2; nt++)
#pragma unroll
            for (int e = 0; e < 4; e++) acc_ac[mt][nt][e] = 0.0f;
#pragma unroll
        for (int nt = 0; nt < 4; nt++)
#pragma unroll
            for (int e = 0; e < 4; e++) acc_w[mt][nt][e] = 0.0f;
    }

    for (int kk = 0; kk < 64; kk += 32) {
        __syncthreads();
        // q -> QU/QV tiles
#pragma unroll
        for (int l = 0; l < 2; l++) {
            int idx = tid + l * 256;
            int row = idx >> 3;
            int c4  = idx & 7;
            float4 q4 = *(const float4*)(qbase + (size_t)(i0 + row) * 1024 + kk + c4 * 4);
            float4 u4 = *(float4*)&ush[kk + c4 * 4];
            float4 v4 = *(float4*)&vsh[kk + c4 * 4];
            uint32_t h0, l0, h1, l1;
            split2(q4.x + u4.x, q4.y + u4.y, h0, l0);
            split2(q4.z + u4.z, q4.w + u4.w, h1, l1);
            *(uint2*)&QUH[row * SSTR + c4 * 2] = make_uint2(h0, h1);
            *(uint2*)&QUL[row * SSTR + c4 * 2] = make_uint2(l0, l1);
            split2(q4.x + v4.x, q4.y + v4.y, h0, l0);
            split2(q4.z + v4.z, q4.w + v4.w, h1, l1);
            *(uint2*)&QVH[row * SSTR + c4 * 2] = make_uint2(h0, h1);
            *(uint2*)&QVL[row * SSTR + c4 * 2] = make_uint2(l0, l1);
        }
        // k tile
#pragma unroll
        for (int l = 0; l < 2; l++) {
            int idx = tid + l * 256;
            int row = idx >> 3;
            int c4  = idx & 7;
            float4 k4 = *(const float4*)(kbase + (size_t)(j0 + row) * 1024 + kk + c4 * 4);
            uint32_t h0, l0, h1, l1;
            split2(k4.x, k4.y, h0, l0);
            split2(k4.z, k4.w, h1, l1);
            *(uint2*)&KH[row * SSTR + c4 * 2] = make_uint2(h0, h1);
            *(uint2*)&KL[row * SSTR + c4 * 2] = make_uint2(l0, l1);
        }
        // p window (Toeplitz gather)
#pragma unroll
        for (int l = 0; l < 4; l++) {
            int idx = tid + l * 256;
            int row = idx >> 3;           // 0..127
            int c4  = idx & 7;
            int d   = i0 - j0 + row - 63;
            int ad  = d < 0 ? -d : d;
            if (ad > 1023) ad = 1023;
            int pidx = 1023 - ad;
            float4 p4 = *(const float4*)(pbase + (size_t)pidx * 1024 + kk + c4 * 4);
            uint32_t h0, l0, h1, l1;
            split2(p4.x, p4.y, h0, l0);
            split2(p4.z, p4.w, h1, l1);
            *(uint2*)&PH[row * SSTR + c4 * 2] = make_uint2(h0, h1);
            *(uint2*)&PL[row * SSTR + c4 * 2] = make_uint2(l0, l1);
        }
        __syncthreads();

#pragma unroll
        for (int ks = 0; ks < 2; ks++) {
            const int p0 = ks * 8 + tg;
            const int p1 = p0 + 4;
            uint32_t quh[2][4], qul[2][4], qvh[2][4], qvl[2][4];
#pragma unroll
            for (int mt = 0; mt < 2; mt++) {
                int r = wr * 32 + mt * 16 + g;
                quh[mt][0] = QUH[r * SSTR + p0];
                quh[mt][1] = QUH[(r + 8) * SSTR + p0];
                quh[mt][2] = QUH[r * SSTR + p1];
                quh[mt][3] = QUH[(r + 8) * SSTR + p1];
                qul[mt][0] = QUL[r * SSTR + p0];
                qul[mt][1] = QUL[(r + 8) * SSTR + p0];
                qul[mt][2] = QUL[r * SSTR + p1];
                qul[mt][3] = QUL[(r + 8) * SSTR + p1];
                qvh[mt][0] = QVH[r * SSTR + p0];
                qvh[mt][1] = QVH[(r + 8) * SSTR + p0];
                qvh[mt][2] = QVH[r * SSTR + p1];
                qvh[mt][3] = QVH[(r + 8) * SSTR + p1];
                qvl[mt][0] = QVL[r * SSTR + p0];
                qvl[mt][1] = QVL[(r + 8) * SSTR + p0];
                qvl[mt][2] = QVL[r * SSTR + p1];
                qvl[mt][3] = QVL[(r + 8) * SSTR + p1];
            }
            uint32_t kh[2][2], kl[2][2];
#pragma unroll
            for (int nt = 0; nt < 2; nt++) {
                int n = wc * 16 + nt * 8 + g;
                kh[nt][0] = KH[n * SSTR + p0];
                kh[nt][1] = KH[n * SSTR + p1];
                kl[nt][0] = KL[n * SSTR + p0];
                kl[nt][1] = KL[n * SSTR + p1];
            }
            uint32_t ph[4][2], pl[4][2];
#pragma unroll
            for (int nt = 0; nt < 4; nt++) {
                int n = wc * 32 + nt * 8 + g;
                ph[nt][0] = PH[n * SSTR + p0];
                ph[nt][1] = PH[n * SSTR + p1];
                pl[nt][0] = PL[n * SSTR + p0];
                pl[nt][1] = PL[n * SSTR + p1];
            }
#pragma unroll
            for (int mt = 0; mt < 2; mt++) {
#pragma unroll
                for (int nt = 0; nt < 2; nt++) {
                    mma16(acc_ac[mt][nt], quh[mt], kh[nt]);
                    mma16(acc_ac[mt][nt], quh[mt], kl[nt]);
                    mma16(acc_ac[mt][nt], qul[mt], kh[nt]);
                }
#pragma unroll
                for (int nt = 0; nt < 4; nt++) {
                    mma16(acc_w[mt][nt], qvh[mt], ph[nt]);
                    mma16(acc_w[mt][nt], qvh[mt], pl[nt]);
                    mma16(acc_w[mt][nt], qvl[mt], ph[nt]);
                }
            }
        }
    }

    // dump W-gemm accumulators to smem for the Toeplitz gather
    __syncthreads();
#pragma unroll
    for (int mt = 0; mt < 2; mt++)
#pragma unroll
        for (int nt = 0; nt < 4; nt++) {
            int r = wr * 32 + mt * 16 + g;
            int c = wc * 32 + nt * 8 + tg * 2;
            *(float2*)&Wsm[r * 130 + c] = make_float2(acc_w[mt][nt][0], acc_w[mt][nt][1]);
            *(float2*)&Wsm[(r + 8) * 130 + c] = make_float2(acc_w[mt][nt][2], acc_w[mt][nt][3]);
        }
    __syncthreads();

    float* srow = g_s + ((size_t)bh << 20);
#pragma unroll
    for (int mt = 0; mt < 2; mt++)
#pragma unroll
        for (int nt = 0; nt < 2; nt++) {
            int il = wr * 32 + mt * 16 + g;
            int jl = wc * 16 + nt * 8 + tg * 2;
            {
                int d = il - jl + 63;
                float v0 = (acc_ac[mt][nt][0] + Wsm[il * 130 + d]) * 0.125f;
                float v1 = (acc_ac[mt][nt][1] + Wsm[il * 130 + d - 1]) * 0.125f;
                *(float2*)(srow + (size_t)(i0 + il) * 1024 + j0 + jl) = make_float2(v0, v1);
            }
            {
                int il2 = il + 8;
                int d = il2 - jl + 63;
                float v0 = (acc_ac[mt][nt][2] + Wsm[il2 * 130 + d]) * 0.125f;
                float v1 = (acc_ac[mt][nt][3] + Wsm[il2 * 130 + d - 1]) * 0.125f;
                *(float2*)(srow + (size_t)(i0 + il2) * 1024 + j0 + jl) = make_float2(v0, v1);
            }
        }
}

// ============================================================================
// Row softmax over g_s (32768 rows of 1024), in place.
// ============================================================================
__global__ __launch_bounds__(256) void softmax_kernel()
{
    __shared__ float redm[8];
    __shared__ float reds[8];
    const size_t row = blockIdx.x;
    float4* p4 = (float4*)(g_s + (row << 10));
    const int tid  = threadIdx.x;
    const int lane = tid & 31;
    const int wid  = tid >> 5;

    float4 v = p4[tid];
    float m = fmaxf(fmaxf(v.x, v.y), fmaxf(v.z, v.w));
#pragma unroll
    for (int o = 16; o; o >>= 1) m = fmaxf(m, __shfl_xor_sync(0xffffffffu, m, o));
    if (lane == 0) redm[wid] = m;
    __syncthreads();
    float bm = redm[0];
#pragma unroll
    for (int i = 1; i < 8; i++) bm = fmaxf(bm, redm[i]);

    v.x = expf(v.x - bm);
    v.y = expf(v.y - bm);
    v.z = expf(v.z - bm);
    v.w = expf(v.w - bm);
    float s = v.x + v.y + v.z + v.w;
#pragma unroll
    for (int o = 16; o; o >>= 1) s += __shfl_xor_sync(0xffffffffu, s, o);
    if (lane == 0) reds[wid] = s;
    __syncthreads();
    float tot = 0.0f;
#pragma unroll
    for (int i = 0; i < 8; i++) tot += reds[i];
    float inv = 1.0f / tot;
    v.x *= inv; v.y *= inv; v.z *= inv; v.w *= inv;
    p4[tid] = v;
}

// ============================================================================
// PV: x[b][t][h*64+d] = sum_s attn[bh][t][s] * V[b][s][h*64+d]
// 128(i) x 64(d) per block, 8 warps x 16 rows, BK=32.
// ============================================================================
#define VSTR 20

__global__ __launch_bounds__(256, 1) void pv_mma()
{
    const int i0 = blockIdx.x * 128;
    const int bh = blockIdx.y;
    const int b  = bh >> 4;
    const int h  = bh & 15;

    __shared__ uint32_t AshH[128 * VSTR], AshL[128 * VSTR];
    __shared__ uint32_t BshH[64 * VSTR], BshL[64 * VSTR];

    const int tid  = threadIdx.x;
    const int warp = tid >> 5;
    const int lane = tid & 31;
    const int g    = lane >> 2;
    const int tg   = lane & 3;

    float acc[8][4];
#pragma unroll
    for (int nt = 0; nt < 8; nt++)
#pragma unroll
        for (int e = 0; e < 4; e++) acc[nt][e] = 0.0f;

    const float* sbase = g_s + ((size_t)bh << 20);
    const float* vbase = g_v + (size_t)(b * 1024) * 1024 + h * 64;

    for (int s0 = 0; s0 < 1024; s0 += 32) {
        __syncthreads();
        // attn tile 128x32
#pragma unroll
        for (int l = 0; l < 4; l++) {
            int idx = tid + l * 256;
            int row = idx >> 3;
            int c4  = idx & 7;
            float4 a = *(const float4*)(sbase + (size_t)(i0 + row) * 1024 + s0 + c4 * 4);
            uint32_t h0, l0, h1, l1;
            split2(a.x, a.y, h0, l0);
            split2(a.z, a.w, h1, l1);
            *(uint2*)&AshH[row * VSTR + c4 * 2] = make_uint2(h0, h1);
            *(uint2*)&AshL[row * VSTR + c4 * 2] = make_uint2(l0, l1);
        }
        // V tile 32x64 packed pair-along-s: Bsh[d][pair]
#pragma unroll
        for (int l = 0; l < 4; l++) {
            int idx = tid + l * 256;    // 0..1023
            int d = idx & 63;
            int p = idx >> 6;           // 0..15
            float v0 = vbase[(size_t)(s0 + 2 * p) * 1024 + d];
            float v1 = vbase[(size_t)(s0 + 2 * p + 1) * 1024 + d];
            uint32_t hh, ll;
            split2(v0, v1, hh, ll);
            BshH[d * VSTR + p] = hh;
            BshL[d * VSTR + p] = ll;
        }
        __syncthreads();

#pragma unroll
        for (int ks = 0; ks < 2; ks++) {
            const int p0 = ks * 8 + tg;
            const int p1 = p0 + 4;
            uint32_t ah[4], al4[4];
            int r = warp * 16 + g;
            ah[0] = AshH[r * VSTR + p0];
            ah[1] = AshH[(r + 8) * VSTR + p0];
            ah[2] = AshH[r * VSTR + p1];
            ah[3] = AshH[(r + 8) * VSTR + p1];
            al4[0] = AshL[r * VSTR + p0];
            al4[1] = AshL[(r + 8) * VSTR + p0];
            al4[2] = AshL[r * VSTR + p1];
            al4[3] = AshL[(r + 8) * VSTR + p1];
#pragma unroll
            for (int nt = 0; nt < 8; nt++) {
                int n = nt * 8 + g;
                uint32_t bhf[2], blf[2];
                bhf[0] = BshH[n * VSTR + p0];
                bhf[1] = BshH[n * VSTR + p1];
                blf[0] = BshL[n * VSTR + p0];
                blf[1] = BshL[n * VSTR + p1];
                mma16(acc[nt], ah, bhf);
                mma16(acc[nt], ah, blf);
                mma16(acc[nt], al4, bhf);
            }
        }
    }

#pragma unroll
    for (int nt = 0; nt < 8; nt++) {
        int row = b * 1024 + i0 + warp * 16 + g;
        int col = h * 64 + nt * 8 + tg * 2;
        *(float2*)(g_x + (size_t)row * 1024 + col) = make_float2(acc[nt][0], acc[nt][1]);
        *(float2*)(g_x + (size_t)(row + 8) * 1024 + col) = make_float2(acc[nt][2], acc[nt][3]);
    }
}

// ============================================================================
// Host launcher
// ============================================================================
extern "C" void kernel_launch(void* const* d_in, const int* in_sizes, int n_in,
                              void* d_out, int out_size)
{
    const float* query   = (const float*)d_in[0];
    const float* key     = (const float*)d_in[1];
    const float* value   = (const float*)d_in[2];
    const float* pos_emb = (const float*)d_in[3];
    const float* Wq = (const float*)d_in[4];
    const float* bq = (const float*)d_in[5];
    const float* Wk = (const float*)d_in[6];
    const float* bk = (const float*)d_in[7];
    const float* Wv = (const float*)d_in[8];
    const float* bv = (const float*)d_in[9];
    const float* Wp = (const float*)d_in[10];
    const float* bp = (const float*)d_in[11];
    const float* Wo = (const float*)d_in[12];
    const float* bo = (const float*)d_in[13];
    const float* u_bias = (const float*)d_in[14];
    const float* v_bias = (const float*)d_in[15];
    float* out = (float*)d_out;

    static float *pq = nullptr, *pk = nullptr, *pvv = nullptr, *pp = nullptr, *px = nullptr;
    if (!pq) {
        cudaGetSymbolAddress((void**)&pq, g_q);
        cudaGetSymbolAddress((void**)&pk, g_k);
        cudaGetSymbolAddress((void**)&pvv, g_v);
        cudaGetSymbolAddress((void**)&pp, g_p);
        cudaGetSymbolAddress((void**)&px, g_x);
    }

    dim3 blk(256);
    gemm_bias_mma<<<dim3(8, 16), blk>>>(query,   Wq, bq, pq);
    gemm_bias_mma<<<dim3(8, 16), blk>>>(key,     Wk, bk, pk);
    gemm_bias_mma<<<dim3(8, 16), blk>>>(value,   Wv, bv, pvv);
    gemm_bias_mma<<<dim3(8, 8),  blk>>>(pos_emb, Wp, bp, pp);
    scores_mma<<<dim3(16, 16, 32), blk>>>(u_bias, v_bias);
    softmax_kernel<<<32768, 256>>>();
    pv_mma<<<dim3(8, 32), blk>>>();
    gemm_bias_mma<<<dim3(8, 16), blk>>>(px, Wo, bo, out);
}